// round 2
// baseline (speedup 1.0000x reference)
#include <cuda_runtime.h>
#include <cstdint>

// Lightning attention, chunked-parallel formulation:
//   K1: per-chunk KV outer products C_j = (k*k_decay)^T @ v   (1024 independent GEMMs)
//   K2: exclusive decayed prefix-scan of C over chunks -> per-chunk input state S_j
//   K3: O = (Q K^T * causal_decay) @ V + diag(q_decay) (Q @ S_j)  (3 GEMMs/CTA)
// All GEMMs: 128x128x128, tf32 mma.sync (rna-rounded), fp32 accumulate.

#define SF 133            // smem row stride in 4B words (conflict-avoiding pad)
#define NT 256

__device__ float g_state[1024 * 128 * 128];   // 64 MB scratch (chunk states)

__device__ __forceinline__ uint32_t f2tf(float x) {
    uint32_t r;
    asm("cvt.rna.tf32.f32 %0, %1;" : "=r"(r) : "f"(x));
    return r;
}

__device__ __forceinline__ void mma8(float* c, const uint32_t* a, const uint32_t* b) {
    asm volatile(
        "mma.sync.aligned.m16n8k8.row.col.f32.tf32.tf32.f32 "
        "{%0,%1,%2,%3}, {%4,%5,%6,%7}, {%8,%9}, {%0,%1,%2,%3};"
        : "+f"(c[0]), "+f"(c[1]), "+f"(c[2]), "+f"(c[3])
        : "r"(a[0]), "r"(a[1]), "r"(a[2]), "r"(a[3]), "r"(b[0]), "r"(b[1]));
}

// 128x128x128 GEMM on smem tiles. A[m][k] row-major (stride SF), B[k][n] (stride SF).
// Warp tile: 32 (m) x 64 (n); 8 warps cover 128x128.
__device__ __forceinline__ void gemm128(const uint32_t* __restrict__ As,
                                        const uint32_t* __restrict__ Bs,
                                        float acc[2][8][4], int lane, int rb, int cb) {
#pragma unroll
    for (int ks = 0; ks < 16; ks++) {
        const int k0 = ks * 8;
        uint32_t a[2][4];
#pragma unroll
        for (int mt = 0; mt < 2; mt++) {
            int r = rb + mt * 16 + (lane >> 2);
            int c = k0 + (lane & 3);
            a[mt][0] = As[r * SF + c];
            a[mt][1] = As[(r + 8) * SF + c];
            a[mt][2] = As[r * SF + c + 4];
            a[mt][3] = As[(r + 8) * SF + c + 4];
        }
#pragma unroll
        for (int nt = 0; nt < 8; nt++) {
            int n = cb + nt * 8 + (lane >> 2);
            int kk = k0 + (lane & 3);
            uint32_t b[2];
            b[0] = Bs[kk * SF + n];
            b[1] = Bs[(kk + 4) * SF + n];
#pragma unroll
            for (int mt = 0; mt < 2; mt++) mma8(acc[mt][nt], a[mt], b);
        }
    }
}

// ---------------- K1: C_j = (k * k_decay)^T @ v ----------------
__global__ void __launch_bounds__(NT) k_chunkKV(const float* __restrict__ k,
                                               const float* __restrict__ v,
                                               const float* __restrict__ s) {
    extern __shared__ uint32_t sm[];
    uint32_t* As = sm;            // A[d][tau] = kdec(tau)*k[tau][d]
    uint32_t* Bs = sm + 128 * SF; // B[tau][e] = v[tau][e]
    const int g = blockIdx.x;
    const int bh = g >> 5;
    const float sh = __ldg(&s[bh & 15]);
    const size_t base = ((size_t)bh * 4096 + (size_t)(g & 31) * 128) * 128;
    const int tid = threadIdx.x;

    for (int idx = tid; idx < 16384; idx += NT) {
        int row = idx >> 7, col = idx & 127;         // row = tau, col = d/e
        float kd = __expf(-sh * (float)(128 - row));
        As[col * SF + row] = f2tf(k[base + idx] * kd);
        Bs[row * SF + col] = f2tf(v[base + idx]);
    }
    __syncthreads();

    const int warp = tid >> 5, lane = tid & 31;
    const int rb = (warp >> 1) * 32, cb = (warp & 1) * 64;
    float acc[2][8][4] = {};
    gemm128(As, Bs, acc, lane, rb, cb);

    float* C = g_state + (size_t)g * 16384;
#pragma unroll
    for (int mt = 0; mt < 2; mt++)
#pragma unroll
        for (int nt = 0; nt < 8; nt++) {
            int r = rb + mt * 16 + (lane >> 2);
            int c = cb + nt * 8 + (lane & 3) * 2;
            C[r * 128 + c]           = acc[mt][nt][0];
            C[r * 128 + c + 1]       = acc[mt][nt][1];
            C[(r + 8) * 128 + c]     = acc[mt][nt][2];
            C[(r + 8) * 128 + c + 1] = acc[mt][nt][3];
        }
}

// ---------------- K2: exclusive decayed prefix scan over chunks ----------------
__global__ void __launch_bounds__(NT) k_scan(const float* __restrict__ s) {
    const int bh = blockIdx.y;
    const int e = blockIdx.x * NT + threadIdx.x;     // element within 128x128 state
    const float lamB = __expf(-__ldg(&s[bh & 15]) * 128.0f);
    float* base = g_state + (size_t)bh * 32 * 16384 + e;
    float val = 0.0f;
#pragma unroll 1
    for (int j = 0; j < 32; j++) {
        float c = base[(size_t)j * 16384];
        base[(size_t)j * 16384] = val;               // exclusive prefix
        val = lamB * val + c;
    }
}

// ---------------- K3: output ----------------
__global__ void __launch_bounds__(NT) k_output(const float* __restrict__ q,
                                              const float* __restrict__ k,
                                              const float* __restrict__ v,
                                              const float* __restrict__ s,
                                              float* __restrict__ o) {
    extern __shared__ uint32_t sm[];
    uint32_t* Qs = sm;                 // Q[t][d]
    uint32_t* X  = sm + 128 * SF;      // K^T[d][i], later scores[t][i]
    uint32_t* Y  = sm + 2 * 128 * SF;  // S[d][e], later V[i][e]
    const int g = blockIdx.x;
    const int bh = g >> 5;
    const float sh = __ldg(&s[bh & 15]);
    const size_t base = ((size_t)bh * 4096 + (size_t)(g & 31) * 128) * 128;
    const float* S = g_state + (size_t)g * 16384;
    const int tid = threadIdx.x;

    for (int idx = tid; idx < 16384; idx += NT) {
        int row = idx >> 7, col = idx & 127;
        Qs[row * SF + col] = f2tf(q[base + idx]);
        X[col * SF + row]  = f2tf(k[base + idx]);    // transpose: X[d][i]
        Y[row * SF + col]  = f2tf(S[idx]);
    }
    __syncthreads();

    const int warp = tid >> 5, lane = tid & 31;
    const int rb = (warp >> 1) * 32, cb = (warp & 1) * 64;

    // GEMM1: scores = Q @ K^T, then causal decay mask
    float acc[2][8][4] = {};
    gemm128(Qs, X, acc, lane, rb, cb);
#pragma unroll
    for (int mt = 0; mt < 2; mt++)
#pragma unroll
        for (int nt = 0; nt < 8; nt++) {
            int r = rb + mt * 16 + (lane >> 2);
            int c = cb + nt * 8 + (lane & 3) * 2;
            int d00 = r - c, d01 = r - c - 1, d10 = r + 8 - c, d11 = r + 7 - c;
            acc[mt][nt][0] = (d00 >= 0) ? acc[mt][nt][0] * __expf(-sh * (float)d00) : 0.0f;
            acc[mt][nt][1] = (d01 >= 0) ? acc[mt][nt][1] * __expf(-sh * (float)d01) : 0.0f;
            acc[mt][nt][2] = (d10 >= 0) ? acc[mt][nt][2] * __expf(-sh * (float)d10) : 0.0f;
            acc[mt][nt][3] = (d11 >= 0) ? acc[mt][nt][3] * __expf(-sh * (float)d11) : 0.0f;
        }
    __syncthreads();   // all warps done reading X (K^T)
#pragma unroll
    for (int mt = 0; mt < 2; mt++)
#pragma unroll
        for (int nt = 0; nt < 8; nt++) {
            int r = rb + mt * 16 + (lane >> 2);
            int c = cb + nt * 8 + (lane & 3) * 2;
            X[r * SF + c]           = f2tf(acc[mt][nt][0]);
            X[r * SF + c + 1]       = f2tf(acc[mt][nt][1]);
            X[(r + 8) * SF + c]     = f2tf(acc[mt][nt][2]);
            X[(r + 8) * SF + c + 1] = f2tf(acc[mt][nt][3]);
        }
    __syncthreads();

    // GEMM2: o_inter = Q @ S, then row-scale by q_decay
    float out[2][8][4] = {};
    gemm128(Qs, Y, out, lane, rb, cb);
#pragma unroll
    for (int mt = 0; mt < 2; mt++) {
        int r = rb + mt * 16 + (lane >> 2);
        float e0 = __expf(-sh * (float)r);
        float e8 = __expf(-sh * (float)(r + 8));
#pragma unroll
        for (int nt = 0; nt < 8; nt++) {
            out[mt][nt][0] *= e0;
            out[mt][nt][1] *= e0;
            out[mt][nt][2] *= e8;
            out[mt][nt][3] *= e8;
        }
    }
    __syncthreads();   // all warps done reading Y (S)
    for (int idx = tid; idx < 16384; idx += NT) {
        int row = idx >> 7, col = idx & 127;
        Y[row * SF + col] = f2tf(v[base + idx]);     // V[i][e]
    }
    __syncthreads();

    // GEMM3: out += scores @ V
    gemm128(X, Y, out, lane, rb, cb);

#pragma unroll
    for (int mt = 0; mt < 2; mt++)
#pragma unroll
        for (int nt = 0; nt < 8; nt++) {
            int r = rb + mt * 16 + (lane >> 2);
            int c = cb + nt * 8 + (lane & 3) * 2;
            o[base + r * 128 + c]           = out[mt][nt][0];
            o[base + r * 128 + c + 1]       = out[mt][nt][1];
            o[base + (r + 8) * 128 + c]     = out[mt][nt][2];
            o[base + (r + 8) * 128 + c + 1] = out[mt][nt][3];
        }
}

extern "C" void kernel_launch(void* const* d_in, const int* in_sizes, int n_in,
                              void* d_out, int out_size) {
    const float* q = (const float*)d_in[0];
    const float* k = (const float*)d_in[1];
    const float* v = (const float*)d_in[2];
    const float* s = (const float*)d_in[3];
    float* o = (float*)d_out;

    const size_t sm1 = (size_t)2 * 128 * SF * 4;   // 136,192 B
    const size_t sm3 = (size_t)3 * 128 * SF * 4;   // 204,288 B
    cudaFuncSetAttribute(k_chunkKV, cudaFuncAttributeMaxDynamicSharedMemorySize, (int)sm1);
    cudaFuncSetAttribute(k_output,  cudaFuncAttributeMaxDynamicSharedMemorySize, (int)sm3);

    k_chunkKV<<<1024, NT, sm1>>>(k, v, s);
    k_scan<<<dim3(64, 32), NT>>>(s);
    k_output<<<1024, NT, sm3>>>(q, k, v, s, o);
}

// round 4
// speedup vs baseline: 1.2551x; 1.2551x over previous
#include <cuda_runtime.h>
#include <cstdint>

// Lightning attention, chunked-parallel, mma.sync tf32 (row.col) with cp.async fills.
//   K1: C_j = (k*k_decay)^T @ v       (2048 CTAs: 64x128x128 each, 2 per chunk)
//   K2: in-place exclusive decayed prefix scan of C over chunks (-> state S_j)
//   K3: scores=(Q K^T)*mask; O = qdec*(Q@S) + scores@V   (3 GEMMs per CTA)
// All operands live in smem in NATURAL gmem layout; transposes happen via
// transposed fragment indexing. cvt fp32->tf32 (rna) at fragment load.

#define SD  136   // smem row stride in words for 128-col tiles (136%32==8 -> conflict-free)
#define SDK 72    // smem row stride for K1's 64-col k tile   (72%32==8)

__device__ float g_C[1024u * 16384u];   // 64 MB: chunk KV products, then scanned states

__device__ __forceinline__ uint32_t f2tf(float x){
    uint32_t r; asm("cvt.rna.tf32.f32 %0, %1;" : "=r"(r) : "f"(x)); return r;
}
__device__ __forceinline__ uint32_t s2u(const void* p){
    uint32_t a;
    asm("{ .reg .u64 t; cvta.to.shared.u64 t, %1; cvt.u32.u64 %0, t; }" : "=r"(a) : "l"(p));
    return a;
}
__device__ __forceinline__ void cpa16(uint32_t dst, const void* src){
    asm volatile("cp.async.cg.shared.global [%0], [%1], 16;" :: "r"(dst), "l"(src));
}
#define CP_COMMIT() asm volatile("cp.async.commit_group;" ::: "memory")
#define CP_WAIT0()  asm volatile("cp.async.wait_group 0;" ::: "memory")

__device__ __forceinline__ void mma8(float* c, const uint32_t* a, const uint32_t* b){
    asm volatile(
        "mma.sync.aligned.m16n8k8.row.col.f32.tf32.tf32.f32 "
        "{%0,%1,%2,%3}, {%4,%5,%6,%7}, {%8,%9}, {%0,%1,%2,%3};"
        : "+f"(c[0]), "+f"(c[1]), "+f"(c[2]), "+f"(c[3])
        : "r"(a[0]), "r"(a[1]), "r"(a[2]), "r"(a[3]), "r"(b[0]), "r"(b[1]));
}

// 32x32x128 warp GEMM. A[m][k] (or transposed-stored if AT: element (m,k) at A[k*sa+m]),
// B[k][n] (or BT: element (k,n) at B[n*sb+k]). Optional per-k scale table (SC).
template<bool AT, bool SC, bool BT>
__device__ __forceinline__ void gemm32(const float* __restrict__ A, int sa,
                                       const float* __restrict__ B, int sb,
                                       const float* __restrict__ kd,
                                       float acc[2][4][4], int rb, int cb, int lane){
    const int lr = lane >> 2, lc = lane & 3;
#pragma unroll
    for (int ks = 0; ks < 16; ks++){
        const int k0 = ks * 8;
        const int kc = k0 + lc;
        uint32_t a[2][4];
#pragma unroll
        for (int mt = 0; mt < 2; mt++){
            const int m = rb + mt * 16 + lr;
            float a0, a1, a2, a3;
            if (AT){
                a0 = A[kc * sa + m];       a1 = A[kc * sa + m + 8];
                a2 = A[(kc + 4) * sa + m]; a3 = A[(kc + 4) * sa + m + 8];
            } else {
                a0 = A[m * sa + kc];       a1 = A[(m + 8) * sa + kc];
                a2 = A[m * sa + kc + 4];   a3 = A[(m + 8) * sa + kc + 4];
            }
            if (SC){
                float s0 = kd[kc], s4 = kd[kc + 4];
                a0 *= s0; a1 *= s0; a2 *= s4; a3 *= s4;
            }
            a[mt][0] = f2tf(a0); a[mt][1] = f2tf(a1);
            a[mt][2] = f2tf(a2); a[mt][3] = f2tf(a3);
        }
#pragma unroll
        for (int nt = 0; nt < 4; nt++){
            const int n = cb + nt * 8 + lr;
            float b0v, b1v;
            if (BT){ b0v = B[n * sb + kc];  b1v = B[n * sb + kc + 4]; }
            else   { b0v = B[kc * sb + n];  b1v = B[(kc + 4) * sb + n]; }
            uint32_t b[2] = { f2tf(b0v), f2tf(b1v) };
            mma8(acc[0][nt], a[0], b);
            mma8(acc[1][nt], a[1], b);
        }
    }
}

// cp.async a 128-row tile; rowbytes must be a multiple of 16.
__device__ __forceinline__ void fill_tile(uint32_t sdst, const float* gsrc, int gstride_f,
                                          int rowbytes, int sstride_b, int tid, int nthr){
    const int cpr = rowbytes >> 4;
    const int total = 128 * cpr;
    for (int i = tid; i < total; i += nthr){
        int r = i / cpr, c = i - r * cpr;
        cpa16(sdst + r * sstride_b + c * 16, (const char*)gsrc + (size_t)r * gstride_f * 4 + c * 16);
    }
}

// ---------------- K1: C_j = (k * k_decay)^T @ v  (half of d-rows per CTA) ----------------
__global__ void __launch_bounds__(256) k_chunkKV(const float* __restrict__ k,
                                                 const float* __restrict__ v,
                                                 const float* __restrict__ s){
    extern __shared__ float sm[];
    float* kd  = sm;                    // 128 floats
    float* ksm = sm + 128;              // 128 x SDK  (k columns dh*64..dh*64+63)
    float* vsm = ksm + 128 * SDK;       // 128 x SD
    const int tid = threadIdx.x, w = tid >> 5, lane = tid & 31;
    const int g = blockIdx.x >> 1, dh = blockIdx.x & 1, bh = g >> 5;
    const float sh = __ldg(&s[bh & 15]);
    const size_t base = ((size_t)bh * 4096 + (size_t)(g & 31) * 128) * 128;
    const uint32_t sb = s2u(sm);

    fill_tile(sb + 128 * 4, k + base + dh * 64, 128, 256, SDK * 4, tid, 256);
    fill_tile(sb + (128 + 128 * SDK) * 4, v + base, 128, 512, SD * 4, tid, 256);
    CP_COMMIT();
    if (tid < 128) kd[tid] = __expf(-sh * (float)(128 - tid));
    CP_WAIT0();
    __syncthreads();

    const int rb = (w & 1) * 32, cb = (w >> 1) * 32;
    float acc[2][4][4] = {};
    // A[m=d][k=tau] stored transposed (ksm[tau][d]), scaled by kd[tau]; B = v natural.
    gemm32<true, true, false>(ksm, SDK, vsm, SD, kd, acc, rb, cb, lane);

    float* C = g_C + (size_t)g * 16384 + (size_t)dh * 64 * 128;
    const int lr = lane >> 2, lc2 = (lane & 3) * 2;
#pragma unroll
    for (int mt = 0; mt < 2; mt++){
        const int r = rb + mt * 16 + lr;
#pragma unroll
        for (int nt = 0; nt < 4; nt++){
            const int c = cb + nt * 8 + lc2;
            *(float2*)(C + (size_t)r * 128 + c)       = make_float2(acc[mt][nt][0], acc[mt][nt][1]);
            *(float2*)(C + (size_t)(r + 8) * 128 + c) = make_float2(acc[mt][nt][2], acc[mt][nt][3]);
        }
    }
}

// ---------------- K2: in-place exclusive decayed prefix scan over chunks ----------------
__global__ void __launch_bounds__(256) k_scan(const float* __restrict__ s){
    const int bh = blockIdx.y;
    const int e = blockIdx.x * 256 + threadIdx.x;
    const float lamB = __expf(-__ldg(&s[bh & 15]) * 128.0f);
    float* base = g_C + (size_t)bh * 32 * 16384 + e;
    float val = 0.0f;
#pragma unroll 1
    for (int j = 0; j < 32; j++){
        float c = base[(size_t)j * 16384];
        base[(size_t)j * 16384] = val;
        val = lamB * val + c;
    }
}

// ---------------- K3: output ----------------
__global__ void __launch_bounds__(512) k_output(const float* __restrict__ q,
                                                const float* __restrict__ k,
                                                const float* __restrict__ v,
                                                const float* __restrict__ s,
                                                float* __restrict__ o){
    extern __shared__ float sm[];
    float* dec  = sm;                    // 128 floats: exp(-sh * delta)
    float* Qs   = sm + 128;              // 128 x SD : Q
    float* buf1 = Qs + 128 * SD;         // K, then scores
    float* buf2 = buf1 + 128 * SD;       // S, then V
    const int tid = threadIdx.x, w = tid >> 5, lane = tid & 31;
    const int g = blockIdx.x, bh = g >> 5;
    const float sh = __ldg(&s[bh & 15]);
    const size_t base = ((size_t)bh * 4096 + (size_t)(g & 31) * 128) * 128;
    const uint32_t sb = s2u(sm);
    const uint32_t oQ = sb + 128 * 4, o1 = oQ + 128 * SD * 4, o2 = o1 + 128 * SD * 4;
    const float* S = g_C + (size_t)g * 16384;

    fill_tile(oQ, q + base, 128, 512, SD * 4, tid, 512);
    fill_tile(o1, k + base, 128, 512, SD * 4, tid, 512);
    fill_tile(o2, S, 128, 512, SD * 4, tid, 512);
    CP_COMMIT();
    if (tid < 128) dec[tid] = __expf(-sh * (float)tid);
    CP_WAIT0();
    __syncthreads();

    const int rb = (w >> 2) * 32, cb = (w & 3) * 32;
    const int lr = lane >> 2, lc2 = (lane & 3) * 2;

    float acc1[2][4][4] = {};   // scores = Q @ K^T   (B transposed-indexed from K natural)
    gemm32<false, false, true >(Qs, SD, buf1, SD, nullptr, acc1, rb, cb, lane);
    float acc2[2][4][4] = {};   // inter = Q @ S      (S natural [d][e] == [k][n])
    gemm32<false, false, false>(Qs, SD, buf2, SD, nullptr, acc2, rb, cb, lane);
    __syncthreads();            // everyone done reading buf1 (K) and buf2 (S)

    // start V copy into buf2; it overlaps the epilogue below
    fill_tile(o2, v + base, 128, 512, SD * 4, tid, 512);
    CP_COMMIT();

    // epilogue: mask+decay scores -> buf1 (fp32); pre-scale inter by q_decay
#pragma unroll
    for (int mt = 0; mt < 2; mt++){
        const int r = rb + mt * 16 + lr;
        const float e0 = dec[r], e8 = dec[r + 8];
#pragma unroll
        for (int nt = 0; nt < 4; nt++){
            const int c = cb + nt * 8 + lc2;
            float v00 = (r     >= c    ) ? acc1[mt][nt][0] * dec[r - c]     : 0.0f;
            float v01 = (r     >= c + 1) ? acc1[mt][nt][1] * dec[r - c - 1] : 0.0f;
            float v10 = (r + 8 >= c    ) ? acc1[mt][nt][2] * dec[r + 8 - c] : 0.0f;
            float v11 = (r + 8 >= c + 1) ? acc1[mt][nt][3] * dec[r + 7 - c] : 0.0f;
            *(float2*)(buf1 + r * SD + c)       = make_float2(v00, v01);
            *(float2*)(buf1 + (r + 8) * SD + c) = make_float2(v10, v11);
            acc2[mt][nt][0] *= e0; acc2[mt][nt][1] *= e0;
            acc2[mt][nt][2] *= e8; acc2[mt][nt][3] *= e8;
        }
    }
    CP_WAIT0();
    __syncthreads();

    // out = qdec*(Q@S) + scores @ V  (scores natural [t][i], V natural [i][e])
    gemm32<false, false, false>(buf1, SD, buf2, SD, nullptr, acc2, rb, cb, lane);

#pragma unroll
    for (int mt = 0; mt < 2; mt++){
        const int r = rb + mt * 16 + lr;
#pragma unroll
        for (int nt = 0; nt < 4; nt++){
            const int c = cb + nt * 8 + lc2;
            *(float2*)(o + base + (size_t)r * 128 + c)       = make_float2(acc2[mt][nt][0], acc2[mt][nt][1]);
            *(float2*)(o + base + (size_t)(r + 8) * 128 + c) = make_float2(acc2[mt][nt][2], acc2[mt][nt][3]);
        }
    }
}

extern "C" void kernel_launch(void* const* d_in, const int* in_sizes, int n_in,
                              void* d_out, int out_size) {
    const float* q = (const float*)d_in[0];
    const float* k = (const float*)d_in[1];
    const float* v = (const float*)d_in[2];
    const float* s = (const float*)d_in[3];
    float* o = (float*)d_out;

    const int sm1 = (128 + 128 * SDK + 128 * SD) * 4;       // 107,008 B  (2 CTAs/SM)
    const int sm3 = (128 + 3 * 128 * SD) * 4;               // 209,408 B
    cudaFuncSetAttribute(k_chunkKV, cudaFuncAttributeMaxDynamicSharedMemorySize, sm1);
    cudaFuncSetAttribute(k_output,  cudaFuncAttributeMaxDynamicSharedMemorySize, sm3);

    k_chunkKV<<<2048, 256, sm1>>>(k, v, s);
    k_scan<<<dim3(64, 32), 256>>>(s);
    k_output<<<1024, 512, sm3>>>(q, k, v, s, o);
}